// round 10
// baseline (speedup 1.0000x reference)
#include <cuda_runtime.h>

// Photonic mesh simulator, N=128. R10: R7's sync-free warp-per-column layout,
// but each warp now simulates TWO columns via Blackwell packed-f32x2 math
// (fma.rn.f32x2 / mul.rn.f32x2): lane0 = col 2j, lane1 = col 2j+1. All columns
// share identical coefficients & phases, so the packed stream is perfectly
// lane-uniform. Phase table stores (c,c,s,s) per (layer,mode) so one LDG.128
// yields ready packed constants (no splats); (-s,-s) is one 64-bit XOR.
// Copy-free 6-deep ring prefetch; zero barriers; cross via 64-bit shfl.

#define N_ 128
#define NLAYERS 255   // 2N-1
#define RING 6

typedef unsigned long long u64;

// (c,c,s,s) per (layer, mode); + RING+1 padded layers so prefetch never OOBs
__device__ __align__(16) float4 g_tab[(NLAYERS + RING + 1) * N_];

__global__ void precompute_cs_kernel(const float* __restrict__ theta_even) {
    int idx = blockIdx.x * blockDim.x + threadIdx.x;
    if (idx < NLAYERS * N_) {
        float s, c;
        sincosf(theta_even[idx], &s, &c);
        g_tab[idx] = make_float4(c, c, s, s);
    } else if (idx < (NLAYERS + RING + 1) * N_) {
        g_tab[idx] = make_float4(1.0f, 1.0f, 0.0f, 0.0f);  // padding
    }
}

// ---- packed f32x2 helpers ----
__device__ __forceinline__ u64 pk2(float lo, float hi) {
    u64 r; asm("mov.b64 %0, {%1,%2};" : "=l"(r) : "f"(lo), "f"(hi)); return r;
}
__device__ __forceinline__ void upk2(u64 v, float& lo, float& hi) {
    asm("mov.b64 {%0,%1}, %2;" : "=f"(lo), "=f"(hi) : "l"(v));
}
__device__ __forceinline__ u64 fma2(u64 a, u64 b, u64 c) {
    u64 d; asm("fma.rn.f32x2 %0, %1, %2, %3;" : "=l"(d) : "l"(a), "l"(b), "l"(c)); return d;
}
__device__ __forceinline__ u64 mul2(u64 a, u64 b) {
    u64 d; asm("mul.rn.f32x2 %0, %1, %2;" : "=l"(d) : "l"(a), "l"(b)); return d;
}
#define NEG2(v) ((v) ^ 0x8000000080000000ULL)

union F4U { float4 v; u64 p[2]; };
struct Cpx { u64 r, i; };   // packed complex: (re_col0, re_col1), (im_col0, im_col1)

__global__ void __launch_bounds__(32, 1) mesh_warp2_kernel(
    const float* __restrict__ theta_in,
    const float* __restrict__ theta_out,
    float* __restrict__ out)
{
    constexpr float PM = 0.6926399f;   // aM*p
    constexpr float QM = 0.6857478f;   // aM*q
    constexpr float PX = 0.09899495f;  // aX*s
    constexpr float QX = 0.9849873f;   // aX*t
    constexpr float CE = 0.9849873f;   // endpoint scalar

    const int t    = threadIdx.x;      // 0..31
    const int col0 = 2 * blockIdx.x;   // lane0 column
    const int col1 = col0 + 1;         // lane1 column
    const int pbase = 4 * t;           // first pair index owned by this thread

    const u64 PM2  = pk2(PM, PM);
    const u64 QM2  = pk2(QM, QM);
    const u64 NQM2 = pk2(-QM, -QM);
    const u64 PX2  = pk2(PX, PX);
    const u64 QX2  = pk2(QX, QX);
    const u64 NQX2 = pk2(-QX, -QX);
    const u64 CE2  = pk2(CE, CE);
    const u64 Z2   = pk2(0.f, 0.f);

    // state: pair i = rows (2(pbase+i), 2(pbase+i)+1) -> (a[i], b[i]); packed cols
    Cpx a[4], b[4];
    #pragma unroll
    for (int i = 0; i < 4; ++i) { a[i].r = Z2; a[i].i = Z2; b[i].r = Z2; b[i].i = Z2; }

    // init: MMI_IN @ diag(e^{i th_in}); col c excites pair index c
    {
        float s0, c0f, s1, c1f;
        sincosf(theta_in[col0], &s0, &c0f);
        sincosf(theta_in[col1], &s1, &c1f);
        #pragma unroll
        for (int i = 0; i < 4; ++i) {
            int p = pbase + i;
            float arl = (p == col0) ? PM * c0f : 0.f;
            float arh = (p == col1) ? PM * c1f : 0.f;
            float ail = (p == col0) ? PM * s0 : 0.f;
            float aih = (p == col1) ? PM * s1 : 0.f;
            float brl = (p == col0) ? -QM * s0 : 0.f;
            float brh = (p == col1) ? -QM * s1 : 0.f;
            float bil = (p == col0) ? QM * c0f : 0.f;
            float bih = (p == col1) ? QM * c1f : 0.f;
            a[i].r = pk2(arl, arh); a[i].i = pk2(ail, aih);
            b[i].r = pk2(brl, brh); b[i].i = pk2(bil, bih);
        }
    }

    // ring: slot j holds (c,c,s,s) for the 4 owned modes of layer k (k%6==j)
    const float4* tab = g_tab + pbase;   // +mode; layer stride = 128 float4
    F4U q[RING][4];
    #pragma unroll
    for (int j = 0; j < RING; ++j)
        #pragma unroll
        for (int m = 0; m < 4; ++m)
            q[j][m].v = tab[j * N_ + m];

    // phase (even row) + MMI_EVEN on pair i with packed table entry f
    auto layer1 = [&](int i, const F4U& f) {
        u64 c2 = f.p[0], s2 = f.p[1], ns2 = NEG2(s2);
        u64 ar = fma2(a[i].r, c2, mul2(a[i].i, ns2));
        u64 ai = fma2(a[i].r, s2, mul2(a[i].i, c2));
        u64 n0r = fma2(PM2, ar, mul2(NQM2, b[i].i));
        u64 n0i = fma2(PM2, ai, mul2(QM2,  b[i].r));
        u64 n1r = fma2(PM2, b[i].r, mul2(NQM2, ai));
        u64 n1i = fma2(PM2, b[i].i, mul2(QM2,  ar));
        a[i].r = n0r; a[i].i = n0i; b[i].r = n1r; b[i].i = n1i;
    };
    auto layer = [&](const F4U* f) {
        layer1(0, f[0]); layer1(1, f[1]); layer1(2, f[2]); layer1(3, f[3]);
    };

    // CROSS: pairs (2m+1, 2m+2) = (b[m], a[m+1]); endpoints scaled by CE
    auto cross = [&]() {
        u64 pb3r = __shfl_up_sync(0xffffffffu, b[3].r, 1);
        u64 pb3i = __shfl_up_sync(0xffffffffu, b[3].i, 1);
        u64 na0r = __shfl_down_sync(0xffffffffu, a[0].r, 1);
        u64 na0i = __shfl_down_sync(0xffffffffu, a[0].i, 1);

        u64 xb0r = fma2(PX2, b[0].r, mul2(NQX2, a[1].i));
        u64 xb0i = fma2(PX2, b[0].i, mul2(QX2,  a[1].r));
        u64 xa1r = fma2(PX2, a[1].r, mul2(NQX2, b[0].i));
        u64 xa1i = fma2(PX2, a[1].i, mul2(QX2,  b[0].r));
        u64 xb1r = fma2(PX2, b[1].r, mul2(NQX2, a[2].i));
        u64 xb1i = fma2(PX2, b[1].i, mul2(QX2,  a[2].r));
        u64 xa2r = fma2(PX2, a[2].r, mul2(NQX2, b[1].i));
        u64 xa2i = fma2(PX2, a[2].i, mul2(QX2,  b[1].r));
        u64 xb2r = fma2(PX2, b[2].r, mul2(NQX2, a[3].i));
        u64 xb2i = fma2(PX2, b[2].i, mul2(QX2,  a[3].r));
        u64 xa3r = fma2(PX2, a[3].r, mul2(NQX2, b[2].i));
        u64 xa3i = fma2(PX2, a[3].i, mul2(QX2,  b[2].r));

        u64 xa0r, xa0i, xb3r, xb3i;
        if (t > 0) {
            xa0r = fma2(PX2, a[0].r, mul2(NQX2, pb3i));
            xa0i = fma2(PX2, a[0].i, mul2(QX2,  pb3r));
        } else {            // global row 0 endpoint
            xa0r = mul2(CE2, a[0].r);
            xa0i = mul2(CE2, a[0].i);
        }
        if (t < 31) {
            xb3r = fma2(PX2, b[3].r, mul2(NQX2, na0i));
            xb3i = fma2(PX2, b[3].i, mul2(QX2,  na0r));
        } else {            // global row 2N-1 endpoint
            xb3r = mul2(CE2, b[3].r);
            xb3i = mul2(CE2, b[3].i);
        }
        a[0].r = xa0r; a[0].i = xa0i; a[1].r = xa1r; a[1].i = xa1i;
        a[2].r = xa2r; a[2].i = xa2i; a[3].r = xa3r; a[3].i = xa3i;
        b[0].r = xb0r; b[0].i = xb0i; b[1].r = xb1r; b[1].i = xb1i;
        b[2].r = xb2r; b[2].i = xb2i; b[3].r = xb3r; b[3].i = xb3i;
    };

    // mainloop: layers 0..251 in 42 groups of 6; k = 6g+j, cross when j even
    const float4* pre = tab + RING * N_;
    for (int g = 0; g < 42; ++g) {
        #pragma unroll
        for (int j = 0; j < RING; ++j) {
            F4U f[4];
            #pragma unroll
            for (int m = 0; m < 4; ++m) {
                f[m] = q[j][m];
                q[j][m].v = pre[j * N_ + m];   // prefetch layer k+6
            }
            layer(f);
            if ((j & 1) == 0) cross();
        }
        pre += RING * N_;
    }
    // epilogue: layer 252 (slot 0, cross), layer 253 (slot 1)
    layer(q[0]); cross();
    layer(q[1]);

    // Phase(254) only (slot 2)
    #pragma unroll
    for (int i = 0; i < 4; ++i) {
        u64 c2 = q[2][i].p[0], s2 = q[2][i].p[1], ns2 = NEG2(s2);
        u64 ar = fma2(a[i].r, c2, mul2(a[i].i, ns2));
        u64 ai = fma2(a[i].r, s2, mul2(a[i].i, c2));
        a[i].r = ar; a[i].i = ai;
    }

    // MMI_OUT + output phase; float32 output = real part, row-major [m][col]
    #pragma unroll
    for (int i = 0; i < 4; ++i) {
        const int m = pbase + i;
        u64 orr2 = fma2(PM2, a[i].r, mul2(NQM2, b[i].i));
        u64 oii2 = fma2(PM2, a[i].i, mul2(QM2,  b[i].r));
        float o0r, o1r, o0i, o1i;
        upk2(orr2, o0r, o1r);
        upk2(oii2, o0i, o1i);
        float so, co;
        sincosf(theta_out[m], &so, &co);
        out[m * N_ + col0] = fmaf(o0r, co, -o0i * so);
        out[m * N_ + col1] = fmaf(o1r, co, -o1i * so);
    }
}

extern "C" void kernel_launch(void* const* d_in, const int* in_sizes, int n_in,
                              void* d_out, int out_size) {
    // theta_even is the (2N-1)*N array; theta_in first N-sized, theta_out second.
    const float* theta_even = nullptr;
    const float* smalls[2] = {nullptr, nullptr};
    int ns = 0;
    for (int i = 0; i < n_in; ++i) {
        if (in_sizes[i] == NLAYERS * N_) {
            theta_even = (const float*)d_in[i];
        } else if (ns < 2) {
            smalls[ns++] = (const float*)d_in[i];
        }
    }
    const float* theta_in  = smalls[0];
    const float* theta_out = smalls[1];

    precompute_cs_kernel<<<(NLAYERS + RING + 1), N_>>>(theta_even);
    mesh_warp2_kernel<<<N_ / 2, 32>>>(theta_in, theta_out, (float*)d_out);
}

// round 12
// speedup vs baseline: 1.9337x; 1.9337x over previous
#include <cuda_runtime.h>
#include <math.h>

// Photonic mesh simulator, N=128. R12 = R11 resubmit (R11 bench was an infra
// failure: "GB300 container failed twice"; no kernel signal). Math re-audited.
//
// Sync-free warp-per-column (R7 layout) with (a) deferred-scale normalized
// algebra and (b) f32x2 packing of each column's pairs.
//
// Normalization: MMI = PM*[[1,ir],[ir,1]] (r=QM/PM), CROSS = QX*[[r2,i],[i,r2]]
// (r2=PX/QX; endpoint CE == QX so normalized endpoints are identity). The
// scalar factor is re-applied exactly every 16 layers (RS16 = PM^16*QX^8) and
// folded into MMI_OUT for the 14-layer tail. This makes every MMI/cross output
// a single FFMA.
// Packing: thread t owns pairs 4t..4t+3; groups g=0 (pairs 0,1), g=1 (pairs
// 2,3) live in f32x2 lanes (lo=even pair, hi=odd pair). Layers fully packed;
// cross operates scalar on lanes (free register access, no permutes) with 4
// 32-bit shfls at thread boundaries. Zero barriers, zero smem.
// Phase table: (c_lo, c_hi, s_lo, s_hi) per (layer, mode-pair); copy-free
// 8-deep ring prefetch (distance 8 layers >> L2 latency).

#define N_ 128
#define NLAYERS 255   // 2N-1
#define RING 8

typedef unsigned long long u64;

// float4 per (layer, mode-pair u): (c(2u), c(2u+1), s(2u), s(2u+1))
// + RING+1 padded layers so the ring prefetch never goes OOB
__device__ __align__(16) float4 g_tab[(NLAYERS + RING + 1) * (N_ / 2)];

__global__ void precompute_cs_kernel(const float* __restrict__ theta_even) {
    const int L = blockIdx.x;        // layer
    const int u = threadIdx.x;       // mode-pair 0..63
    if (L < NLAYERS) {
        float s0, c0, s1, c1;
        sincosf(theta_even[L * N_ + 2 * u], &s0, &c0);
        sincosf(theta_even[L * N_ + 2 * u + 1], &s1, &c1);
        g_tab[L * 64 + u] = make_float4(c0, c1, s0, s1);
    } else {
        g_tab[L * 64 + u] = make_float4(1.f, 1.f, 0.f, 0.f);
    }
}

// ---- packed f32x2 helpers ----
__device__ __forceinline__ u64 pk2(float lo, float hi) {
    u64 r; asm("mov.b64 %0, {%1,%2};" : "=l"(r) : "f"(lo), "f"(hi)); return r;
}
__device__ __forceinline__ u64 fma2(u64 a, u64 b, u64 c) {
    u64 d; asm("fma.rn.f32x2 %0, %1, %2, %3;" : "=l"(d) : "l"(a), "l"(b), "l"(c)); return d;
}
__device__ __forceinline__ u64 mul2(u64 a, u64 b) {
    u64 d; asm("mul.rn.f32x2 %0, %1, %2;" : "=l"(d) : "l"(a), "l"(b)); return d;
}

union R2u { u64 v; float f[2]; };
union F4U { float4 v; u64 p[2]; };   // p[0]=(c_lo,c_hi), p[1]=(s_lo,s_hi)

__global__ void __launch_bounds__(32, 1) mesh_kernel(
    const float* __restrict__ theta_in,
    const float* __restrict__ theta_out,
    float* __restrict__ out,
    float PMc, float QMc,     // true MMI coeffs (init only)
    float rC,                 // QM/PM
    float r2C,                // PX/QX
    float RS16c,              // PM^16 * QX^8
    float PMfc, float QMfc)   // PM,QM folded with tail scale PM^14*QX^7
{
    const int t   = threadIdx.x;     // 0..31
    const int col = blockIdx.x;      // column
    const int pbase = 4 * t;         // first owned pair

    const u64 RC2  = pk2(rC, rC);
    const u64 NR2  = pk2(-rC, -rC);
    const u64 M1   = pk2(-1.f, -1.f);
    const u64 RS2  = pk2(RS16c, RS16c);
    const float r2 = r2C;

    // packed state: group0: pairs pbase+0 (lo), pbase+1 (hi);
    //               group1: pairs pbase+2 (lo), pbase+3 (hi)
    R2u Ar[2], Ai[2], Br[2], Bi[2];
    #pragma unroll
    for (int g = 0; g < 2; ++g) { Ar[g].v = 0; Ai[g].v = 0; Br[g].v = 0; Bi[g].v = 0; }

    // init: MMI_IN @ diag(e^{i th_in}); column col excites pair index col
    if (col >= pbase && col < pbase + 4) {
        float si, ci;
        sincosf(theta_in[col], &si, &ci);
        int i = col - pbase;          // 0..3
        int g = i >> 1, l = i & 1;
        Ar[g].f[l] = PMc * ci;  Ai[g].f[l] = PMc * si;
        Br[g].f[l] = -QMc * si; Bi[g].f[l] = QMc * ci;
    }

    // ring: slot j holds the 2 table float4 of layer k (k%8==j)
    const float4* tab = g_tab + 2 * t;   // layer stride = 64 float4
    F4U q[RING][2];
    #pragma unroll
    for (int j = 0; j < RING; ++j) {
        q[j][0].v = tab[j * 64];
        q[j][1].v = tab[j * 64 + 1];
    }

    // normalized layer on group g: phase + [[1,ir],[ir,1]]
    auto layerg = [&](int g, const F4U& f) {
        u64 c2 = f.p[0], s2 = f.p[1];
        u64 nAi = mul2(Ai[g].v, M1);
        u64 ur = fma2(Ar[g].v, c2, mul2(nAi, s2));        // a*cos - a_i*sin
        u64 ui = fma2(Ar[g].v, s2, mul2(Ai[g].v, c2));
        u64 n0r = fma2(NR2, Bi[g].v, ur);                 // u - r*b_i (re)
        u64 n0i = fma2(RC2, Br[g].v, ui);
        u64 n1r = fma2(NR2, ui, Br[g].v);                 // b - r*u_i (re)
        u64 n1i = fma2(RC2, ur, Bi[g].v);
        Ar[g].v = n0r; Ai[g].v = n0i; Br[g].v = n1r; Bi[g].v = n1i;
    };

    // normalized cross: each element: r2*self + i*partner; endpoints identity
    auto cross = [&]() {
        float pb3r = __shfl_up_sync(0xffffffffu, Br[1].f[1], 1);
        float pb3i = __shfl_up_sync(0xffffffffu, Bi[1].f[1], 1);
        float xna0r = __shfl_down_sync(0xffffffffu, Ar[0].f[0], 1);
        float xna0i = __shfl_down_sync(0xffffffffu, Ai[0].f[0], 1);

        float a0r = Ar[0].f[0], a0i = Ai[0].f[0];
        float a1r = Ar[0].f[1], a1i = Ai[0].f[1];
        float a2r = Ar[1].f[0], a2i = Ai[1].f[0];
        float a3r = Ar[1].f[1], a3i = Ai[1].f[1];
        float b0r = Br[0].f[0], b0i = Bi[0].f[0];
        float b1r = Br[0].f[1], b1i = Bi[0].f[1];
        float b2r = Br[1].f[0], b2i = Bi[1].f[0];
        float b3r = Br[1].f[1], b3i = Bi[1].f[1];

        float ya0r = (t == 0) ? a0r : fmaf(r2, a0r, -pb3i);
        float ya0i = (t == 0) ? a0i : fmaf(r2, a0i,  pb3r);
        float ya1r = fmaf(r2, a1r, -b0i), ya1i = fmaf(r2, a1i, b0r);
        float ya2r = fmaf(r2, a2r, -b1i), ya2i = fmaf(r2, a2i, b1r);
        float ya3r = fmaf(r2, a3r, -b2i), ya3i = fmaf(r2, a3i, b2r);
        float yb0r = fmaf(r2, b0r, -a1i), yb0i = fmaf(r2, b0i, a1r);
        float yb1r = fmaf(r2, b1r, -a2i), yb1i = fmaf(r2, b1i, a2r);
        float yb2r = fmaf(r2, b2r, -a3i), yb2i = fmaf(r2, b2i, a3r);
        float yb3r = (t == 31) ? b3r : fmaf(r2, b3r, -xna0i);
        float yb3i = (t == 31) ? b3i : fmaf(r2, b3i,  xna0r);

        Ar[0].f[0] = ya0r; Ai[0].f[0] = ya0i;
        Ar[0].f[1] = ya1r; Ai[0].f[1] = ya1i;
        Ar[1].f[0] = ya2r; Ai[1].f[0] = ya2i;
        Ar[1].f[1] = ya3r; Ai[1].f[1] = ya3i;
        Br[0].f[0] = yb0r; Bi[0].f[0] = yb0i;
        Br[0].f[1] = yb1r; Bi[0].f[1] = yb1i;
        Br[1].f[0] = yb2r; Bi[1].f[0] = yb2i;
        Br[1].f[1] = yb3r; Bi[1].f[1] = yb3i;
    };

    // mainloop: 15 groups x 16 layers (0..239); exact rescale RS16 per group
    for (int g = 0; g < 15; ++g) {
        const int k0 = 16 * g;
        #pragma unroll
        for (int j = 0; j < 16; ++j) {
            const int sl = j & 7;
            F4U f0 = q[sl][0], f1 = q[sl][1];
            q[sl][0].v = tab[(k0 + j + RING) * 64];       // prefetch layer k+8
            q[sl][1].v = tab[(k0 + j + RING) * 64 + 1];
            layerg(0, f0);
            layerg(1, f1);
            if ((j & 1) == 0) cross();                    // k even <=> j even
        }
        #pragma unroll
        for (int gg = 0; gg < 2; ++gg) {                  // exact rescale
            Ar[gg].v = mul2(Ar[gg].v, RS2);
            Ai[gg].v = mul2(Ai[gg].v, RS2);
            Br[gg].v = mul2(Br[gg].v, RS2);
            Bi[gg].v = mul2(Bi[gg].v, RS2);
        }
    }
    // tail: layers 240..253 (7 crosses); scale folded into PMf/QMf below
    #pragma unroll
    for (int j = 0; j < 14; ++j) {
        const int sl = j & 7;
        F4U f0 = q[sl][0], f1 = q[sl][1];
        q[sl][0].v = tab[(240 + j + RING) * 64];
        q[sl][1].v = tab[(240 + j + RING) * 64 + 1];
        layerg(0, f0);
        layerg(1, f1);
        if ((j & 1) == 0) cross();
    }

    // Phase(254) only: slot 254&7 = 6
    #pragma unroll
    for (int g = 0; g < 2; ++g) {
        u64 c2 = q[6][g].p[0], s2 = q[6][g].p[1];
        u64 nAi = mul2(Ai[g].v, M1);
        u64 ur = fma2(Ar[g].v, c2, mul2(nAi, s2));
        u64 ui = fma2(Ar[g].v, s2, mul2(Ai[g].v, c2));
        Ar[g].v = ur; Ai[g].v = ui;
    }

    // MMI_OUT (with folded tail scale) + output phase; output = real part
    #pragma unroll
    for (int i = 0; i < 4; ++i) {
        const int g = i >> 1, l = i & 1;
        const int m = pbase + i;
        float orr = fmaf(PMfc, Ar[g].f[l], -QMfc * Bi[g].f[l]);
        float oii = fmaf(PMfc, Ai[g].f[l],  QMfc * Br[g].f[l]);
        float so, co;
        sincosf(theta_out[m], &so, &co);
        out[m * N_ + col] = fmaf(orr, co, -oii * so);
    }
}

extern "C" void kernel_launch(void* const* d_in, const int* in_sizes, int n_in,
                              void* d_out, int out_size) {
    // theta_even is the (2N-1)*N array; theta_in first N-sized, theta_out second.
    const float* theta_even = nullptr;
    const float* smalls[2] = {nullptr, nullptr};
    int ns = 0;
    for (int i = 0; i < n_in; ++i) {
        if (in_sizes[i] == NLAYERS * N_) {
            theta_even = (const float*)d_in[i];
        } else if (ns < 2) {
            smalls[ns++] = (const float*)d_in[i];
        }
    }
    const float* theta_in  = smalls[0];
    const float* theta_out = smalls[1];

    // exact constants in double, rounded once to float
    const double aM = sqrt(1.0 - 0.05), p = sqrt(0.505), q = sqrt(0.495);
    const double PM = aM * p, QM = aM * q, r = q / p;
    const double aX = sqrt(1.0 - 0.02);
    const double QX = aX * sqrt(0.99);
    const double r2 = sqrt(0.01 / 0.99);
    const double RS16 = pow(PM, 16) * pow(QX, 8);
    const double RSrem = pow(PM, 14) * pow(QX, 7);

    precompute_cs_kernel<<<(NLAYERS + RING + 1), 64>>>(theta_even);
    mesh_kernel<<<N_, 32>>>(theta_in, theta_out, (float*)d_out,
                            (float)PM, (float)QM, (float)r, (float)r2,
                            (float)RS16, (float)(PM * RSrem), (float)(QM * RSrem));
}